// round 4
// baseline (speedup 1.0000x reference)
#include <cuda_runtime.h>
#include <math.h>

// SofaNetEllipse: fused MLP(1->128->128->128->1) forward + JVP + ellipse epilogue.
// Inputs (metadata order): alpha(4097), w0(128*128), w1(128^3), w2(128^3),
//   w3(128*128), b0(128*128), b1(128*128), b2(128*128), b3(128), sqrt_a(128)
// Output: float[4 * 128 * 4097] = [xp; yp; xp_prime; yp_prime]

typedef unsigned long long ull;

namespace {
constexpr int HD      = 128;    // hidden dim
constexpr int NCUR    = 128;    // number of curves
constexpr int LFULL   = 4097;
constexpr int BHALF   = 2049;   // L//2 + 1
constexpr int BT      = 128;    // samples per block tile
constexpr int NTILES  = (BHALF + BT - 1) / BT;  // 17
constexpr int WSTRIDE = 129;    // padded transposed-weight row stride (floats)
constexpr int NTHREADS = 256;
constexpr size_t SMEM_HD    = (size_t)HD * BT * 8;        // 131072 B: {h,dh} f32x2
constexpr size_t SMEM_W     = (size_t)HD * WSTRIDE * 4;   // 66048 B
constexpr size_t SMEM_BYTES = SMEM_HD + SMEM_W;           // 197120 B
}

// packed f32x2 fma (Blackwell sm_100+): d.lo = a.lo*b.lo+c.lo ; d.hi likewise
__device__ __forceinline__ ull ffma2(ull a, ull b, ull c) {
    ull d;
    asm("fma.rn.f32x2 %0, %1, %2, %3;" : "=l"(d) : "l"(a), "l"(b), "l"(c));
    return d;
}
__device__ __forceinline__ ull dup2(float x) {            // {x, x}
    ull r; asm("mov.b64 %0, {%1, %1};" : "=l"(r) : "f"(x)); return r;
}
__device__ __forceinline__ ull pack2(float x, float y) {  // {x, y}
    ull r; asm("mov.b64 %0, {%1, %2};" : "=l"(r) : "f"(x), "f"(y)); return r;
}
__device__ __forceinline__ float2 unpack2(ull v) {
    float lo, hi;
    asm("mov.b64 {%0, %1}, %2;" : "=f"(lo), "=f"(hi) : "l"(v));
    return make_float2(lo, hi);
}

// Stage one 128x128 weight matrix transposed into SMEM: wsh[j*WSTRIDE + i] = W[i][j].
// Coalesced float4 global reads; stride-129 scatter -> ~4-way STS conflicts (cheap, one-shot).
__device__ __forceinline__ void stage_w(float* __restrict__ wsh,
                                        const float* __restrict__ wg, int tid) {
    const float4* g = reinterpret_cast<const float4*>(wg);
    const int j4 = tid & 31;        // which group of 4 columns
    const int i0 = tid >> 5;        // base row
#pragma unroll
    for (int k = 0; k < 16; k++) {
        const int i = i0 + k * 8;
        const float4 v = g[i * 32 + j4];
        const int j = j4 * 4;
        wsh[(j + 0) * WSTRIDE + i] = v.x;
        wsh[(j + 1) * WSTRIDE + i] = v.y;
        wsh[(j + 2) * WSTRIDE + i] = v.z;
        wsh[(j + 3) * WSTRIDE + i] = v.w;
    }
}

// One hidden layer (value + tangent fused in f32x2 lanes), relu + relu-mask.
// hd: interleaved state {h, dh} as ull, layout [j(128)][b(128)].
// wsh: transposed weights. Internal barrier separates the GEMM reads from the
// in-place state overwrite; caller must __syncthreads() after (and may stage
// the next W between return and that barrier — disjoint SMEM region).
__device__ __forceinline__ void dense_relu_layer(ull* __restrict__ hd,
                                                 const float* __restrict__ wsh,
                                                 const float* __restrict__ bias_g,
                                                 int ibase, int bg) {
    ull acc[8][8];
#pragma unroll
    for (int r = 0; r < 8; r++)
#pragma unroll
        for (int p = 0; p < 8; p++) acc[r][p] = 0ull;

#pragma unroll 1
    for (int j = 0; j < HD; j++) {
        const float* wr = wsh + j * WSTRIDE + ibase;
        ull wd[8];
#pragma unroll
        for (int r = 0; r < 8; r++) wd[r] = dup2(wr[r]);
        const ull* hrow = hd + j * BT + bg;     // b = bg + 16*p -> conflict-free
        ull hv[8];
#pragma unroll
        for (int p = 0; p < 8; p++) hv[p] = hrow[16 * p];
#pragma unroll
        for (int r = 0; r < 8; r++)
#pragma unroll
            for (int p = 0; p < 8; p++)
                acc[r][p] = ffma2(wd[r], hv[p], acc[r][p]);
    }

    float bb[8];
#pragma unroll
    for (int r = 0; r < 8; r++) bb[r] = bias_g[ibase + r];

    __syncthreads();   // all GEMM reads of hd/wsh complete before overwrite

#pragma unroll
    for (int r = 0; r < 8; r++) {
#pragma unroll
        for (int p = 0; p < 8; p++) {
            const float2 a = unpack2(acc[r][p]);
            const float pre = a.x + bb[r];
            const float h = pre > 0.f ? pre : 0.f;
            const float d = pre > 0.f ? a.y : 0.f;   // relu JVP mask
            hd[(ibase + r) * BT + bg + 16 * p] = pack2(h, d);
        }
    }
}

__global__ void __launch_bounds__(NTHREADS, 1)
sofa_kernel(const float* __restrict__ alpha,
            const float* __restrict__ w0g, const float* __restrict__ w1g,
            const float* __restrict__ w2g, const float* __restrict__ w3g,
            const float* __restrict__ b0g, const float* __restrict__ b1g,
            const float* __restrict__ b2g, const float* __restrict__ b3g,
            const float* __restrict__ sqrtag, float* __restrict__ out) {
    extern __shared__ char smem_raw[];
    ull*   hd  = reinterpret_cast<ull*>(smem_raw);
    float* wsh = reinterpret_cast<float*>(smem_raw + SMEM_HD);

    const int n    = blockIdx.y;
    const int tile = blockIdx.x;
    const int tid  = threadIdx.x;
    const int bg   = tid & 15;       // b-group: samples b = bg + 16*p
    const int ig   = tid >> 4;       // i-group: rows ibase..ibase+7
    const int ibase = ig * 8;
    const int base  = tile * BT;     // first (half-)sample of this tile

    // ---- layer 0: h0 = relu(w0*alpha + b0), dh0 = mask * w0 ; stage W1
    for (int idx = tid; idx < HD * BT; idx += NTHREADS) {
        const int i = idx >> 7;
        const int b = idx & 127;
        const float av  = alpha[base + b];     // base+b <= 2175 < 4097, in-bounds
        const float w   = w0g[n * HD + i];
        const float bb  = b0g[n * HD + i];
        const float pre = fmaf(w, av, bb);
        const float h   = pre > 0.f ? pre : 0.f;
        const float d   = pre > 0.f ? w : 0.f;
        hd[i * BT + b] = pack2(h, d);
    }
    stage_w(wsh, w1g + (size_t)n * HD * HD, tid);
    __syncthreads();

    // ---- layers 1, 2
    dense_relu_layer(hd, wsh, b1g + n * HD, ibase, bg);
    stage_w(wsh, w2g + (size_t)n * HD * HD, tid);   // wsh dead after internal barrier
    __syncthreads();

    dense_relu_layer(hd, wsh, b2g + n * HD, ibase, bg);
    __syncthreads();

    // ---- layer 3: out = w3 . h2 + b3 ; dout = w3 . dh2 ; then ellipse epilogue
    {
        const int bl = tid & 127;
        const int q  = tid >> 7;               // split reduction over i in halves
        const float* w3n = w3g + n * HD;
        float sv = 0.f, st = 0.f;
#pragma unroll 4
        for (int ii = q * 64; ii < q * 64 + 64; ii++) {
            const float wv = w3n[ii];
            const float2 h = unpack2(hd[ii * BT + bl]);
            sv = fmaf(wv, h.x, sv);
            st = fmaf(wv, h.y, st);
        }
        float* redv = wsh;                      // reuse weight SMEM (dead)
        float* redt = wsh + 2 * BT;
        redv[q * BT + bl] = sv;
        redt[q * BT + bl] = st;
        __syncthreads();

        if (tid < BT) {
            const int jg = base + tid;          // global half-sample index
            if (jg < BHALF) {
                const float v   = redv[tid] + redv[BT + tid] + b3g[n];
                const float t   = redt[tid] + redt[BT + tid];
                const float bsq = v * v;                 // b
                const float dbv = 2.f * v * t;           // db (chain rule of square)
                float a = sqrtag[n]; a = a * a;          // a_full
                const size_t NL = (size_t)NCUR * LFULL;

                float s, c;
                sincosf(alpha[jg], &s, &c);
                const size_t o = (size_t)n * LFULL + jg;
                out[o]          = a * (c - 1.f);         // xp
                out[NL + o]     = bsq * s;               // yp
                out[2 * NL + o] = -a * s;                // xp'
                out[3 * NL + o] = fmaf(bsq, c, dbv * s); // yp'

                if (jg < BHALF - 1) {                    // mirror l = 4096 - jg
                    const int l = 2 * (BHALF - 1) - jg;
                    float s2, c2;
                    sincosf(alpha[l], &s2, &c2);
                    const size_t o2 = (size_t)n * LFULL + l;
                    out[o2]          = a * (c2 - 1.f);
                    out[NL + o2]     = bsq * s2;
                    out[2 * NL + o2] = -a * s2;
                    out[3 * NL + o2] = fmaf(bsq, c2, -dbv * s2);  // db mirrored with -
                }
            }
        }
    }
}

extern "C" void kernel_launch(void* const* d_in, const int* in_sizes, int n_in,
                              void* d_out, int out_size) {
    (void)in_sizes; (void)n_in; (void)out_size;
    const float* alpha  = (const float*)d_in[0];
    const float* w0     = (const float*)d_in[1];
    const float* w1     = (const float*)d_in[2];
    const float* w2     = (const float*)d_in[3];
    const float* w3     = (const float*)d_in[4];
    const float* b0     = (const float*)d_in[5];
    const float* b1     = (const float*)d_in[6];
    const float* b2     = (const float*)d_in[7];
    const float* b3     = (const float*)d_in[8];
    const float* sqrt_a = (const float*)d_in[9];
    float* out = (float*)d_out;

    cudaFuncSetAttribute(sofa_kernel, cudaFuncAttributeMaxDynamicSharedMemorySize,
                         (int)SMEM_BYTES);

    dim3 grid(NTILES, NCUR);   // (17, 128)
    sofa_kernel<<<grid, NTHREADS, SMEM_BYTES>>>(alpha, w0, w1, w2, w3,
                                                b0, b1, b2, b3, sqrt_a, out);
}

// round 5
// speedup vs baseline: 1.0022x; 1.0022x over previous
#include <cuda_runtime.h>
#include <math.h>

// SofaNetEllipse: fused MLP(1->128->128->128->1) forward + JVP + ellipse epilogue.
// Inputs (metadata order): alpha(4097), w0(128*128), w1(128^3), w2(128^3),
//   w3(128*128), b0(128*128), b1(128*128), b2(128*128), b3(128), sqrt_a(128)
// Output: float[4 * 128 * 4097] = [xp; yp; xp_prime; yp_prime]

typedef unsigned long long ull;

namespace {
constexpr int HD      = 128;    // hidden dim
constexpr int NCUR    = 128;    // number of curves
constexpr int LFULL   = 4097;
constexpr int BHALF   = 2049;   // L//2 + 1
constexpr int BT      = 128;    // samples per block tile
constexpr int NTILES  = (BHALF + BT - 1) / BT;  // 17
constexpr int WSTRIDE = 129;    // padded transposed-weight row stride (floats)
constexpr int NTHREADS = 256;
constexpr size_t SMEM_HD    = (size_t)HD * BT * 8;        // 131072 B: {h,dh} f32x2
constexpr size_t SMEM_W     = (size_t)HD * WSTRIDE * 4;   // 66048 B
constexpr size_t SMEM_BYTES = SMEM_HD + SMEM_W;           // 197120 B
}

// packed f32x2 fma (Blackwell sm_100+): d.lo = a.lo*b.lo+c.lo ; d.hi likewise
__device__ __forceinline__ ull ffma2(ull a, ull b, ull c) {
    ull d;
    asm("fma.rn.f32x2 %0, %1, %2, %3;" : "=l"(d) : "l"(a), "l"(b), "l"(c));
    return d;
}
__device__ __forceinline__ ull dup2(float x) {            // {x, x}
    ull r; asm("mov.b64 %0, {%1, %1};" : "=l"(r) : "f"(x)); return r;
}
__device__ __forceinline__ ull pack2(float x, float y) {  // {x, y}
    ull r; asm("mov.b64 %0, {%1, %2};" : "=l"(r) : "f"(x), "f"(y)); return r;
}
__device__ __forceinline__ float2 unpack2(ull v) {
    float lo, hi;
    asm("mov.b64 {%0, %1}, %2;" : "=f"(lo), "=f"(hi) : "l"(v));
    return make_float2(lo, hi);
}

// Stage one 128x128 weight matrix transposed into SMEM: wsh[j*WSTRIDE + i] = W[i][j].
// Coalesced float4 global reads; stride-129 scatter -> ~4-way STS conflicts (cheap, one-shot).
__device__ __forceinline__ void stage_w(float* __restrict__ wsh,
                                        const float* __restrict__ wg, int tid) {
    const float4* g = reinterpret_cast<const float4*>(wg);
    const int j4 = tid & 31;        // which group of 4 columns
    const int i0 = tid >> 5;        // base row
#pragma unroll
    for (int k = 0; k < 16; k++) {
        const int i = i0 + k * 8;
        const float4 v = g[i * 32 + j4];
        const int j = j4 * 4;
        wsh[(j + 0) * WSTRIDE + i] = v.x;
        wsh[(j + 1) * WSTRIDE + i] = v.y;
        wsh[(j + 2) * WSTRIDE + i] = v.z;
        wsh[(j + 3) * WSTRIDE + i] = v.w;
    }
}

// One hidden layer (value + tangent fused in f32x2 lanes), relu + relu-mask.
// hd: interleaved state {h, dh} as ull, layout [j(128)][b(128)].
// wsh: transposed weights. Internal barrier separates the GEMM reads from the
// in-place state overwrite; caller must __syncthreads() after (and may stage
// the next W between return and that barrier — disjoint SMEM region).
__device__ __forceinline__ void dense_relu_layer(ull* __restrict__ hd,
                                                 const float* __restrict__ wsh,
                                                 const float* __restrict__ bias_g,
                                                 int ibase, int bg) {
    ull acc[8][8];
#pragma unroll
    for (int r = 0; r < 8; r++)
#pragma unroll
        for (int p = 0; p < 8; p++) acc[r][p] = 0ull;

#pragma unroll 1
    for (int j = 0; j < HD; j++) {
        const float* wr = wsh + j * WSTRIDE + ibase;
        ull wd[8];
#pragma unroll
        for (int r = 0; r < 8; r++) wd[r] = dup2(wr[r]);
        const ull* hrow = hd + j * BT + bg;     // b = bg + 16*p -> conflict-free
        ull hv[8];
#pragma unroll
        for (int p = 0; p < 8; p++) hv[p] = hrow[16 * p];
#pragma unroll
        for (int r = 0; r < 8; r++)
#pragma unroll
            for (int p = 0; p < 8; p++)
                acc[r][p] = ffma2(wd[r], hv[p], acc[r][p]);
    }

    float bb[8];
#pragma unroll
    for (int r = 0; r < 8; r++) bb[r] = bias_g[ibase + r];

    __syncthreads();   // all GEMM reads of hd/wsh complete before overwrite

#pragma unroll
    for (int r = 0; r < 8; r++) {
#pragma unroll
        for (int p = 0; p < 8; p++) {
            const float2 a = unpack2(acc[r][p]);
            const float pre = a.x + bb[r];
            const float h = pre > 0.f ? pre : 0.f;
            const float d = pre > 0.f ? a.y : 0.f;   // relu JVP mask
            hd[(ibase + r) * BT + bg + 16 * p] = pack2(h, d);
        }
    }
}

__global__ void __launch_bounds__(NTHREADS, 1)
sofa_kernel(const float* __restrict__ alpha,
            const float* __restrict__ w0g, const float* __restrict__ w1g,
            const float* __restrict__ w2g, const float* __restrict__ w3g,
            const float* __restrict__ b0g, const float* __restrict__ b1g,
            const float* __restrict__ b2g, const float* __restrict__ b3g,
            const float* __restrict__ sqrtag, float* __restrict__ out) {
    extern __shared__ char smem_raw[];
    ull*   hd  = reinterpret_cast<ull*>(smem_raw);
    float* wsh = reinterpret_cast<float*>(smem_raw + SMEM_HD);

    const int n    = blockIdx.y;
    const int tile = blockIdx.x;
    const int tid  = threadIdx.x;
    const int bg   = tid & 15;       // b-group: samples b = bg + 16*p
    const int ig   = tid >> 4;       // i-group: rows ibase..ibase+7
    const int ibase = ig * 8;
    const int base  = tile * BT;     // first (half-)sample of this tile

    // ---- layer 0: h0 = relu(w0*alpha + b0), dh0 = mask * w0 ; stage W1
    for (int idx = tid; idx < HD * BT; idx += NTHREADS) {
        const int i = idx >> 7;
        const int b = idx & 127;
        const float av  = alpha[base + b];     // base+b <= 2175 < 4097, in-bounds
        const float w   = w0g[n * HD + i];
        const float bb  = b0g[n * HD + i];
        const float pre = fmaf(w, av, bb);
        const float h   = pre > 0.f ? pre : 0.f;
        const float d   = pre > 0.f ? w : 0.f;
        hd[i * BT + b] = pack2(h, d);
    }
    stage_w(wsh, w1g + (size_t)n * HD * HD, tid);
    __syncthreads();

    // ---- layers 1, 2
    dense_relu_layer(hd, wsh, b1g + n * HD, ibase, bg);
    stage_w(wsh, w2g + (size_t)n * HD * HD, tid);   // wsh dead after internal barrier
    __syncthreads();

    dense_relu_layer(hd, wsh, b2g + n * HD, ibase, bg);
    __syncthreads();

    // ---- layer 3: out = w3 . h2 + b3 ; dout = w3 . dh2 ; then ellipse epilogue
    {
        const int bl = tid & 127;
        const int q  = tid >> 7;               // split reduction over i in halves
        const float* w3n = w3g + n * HD;
        float sv = 0.f, st = 0.f;
#pragma unroll 4
        for (int ii = q * 64; ii < q * 64 + 64; ii++) {
            const float wv = w3n[ii];
            const float2 h = unpack2(hd[ii * BT + bl]);
            sv = fmaf(wv, h.x, sv);
            st = fmaf(wv, h.y, st);
        }
        float* redv = wsh;                      // reuse weight SMEM (dead)
        float* redt = wsh + 2 * BT;
        redv[q * BT + bl] = sv;
        redt[q * BT + bl] = st;
        __syncthreads();

        if (tid < BT) {
            const int jg = base + tid;          // global half-sample index
            if (jg < BHALF) {
                const float v   = redv[tid] + redv[BT + tid] + b3g[n];
                const float t   = redt[tid] + redt[BT + tid];
                const float bsq = v * v;                 // b
                const float dbv = 2.f * v * t;           // db (chain rule of square)
                float a = sqrtag[n]; a = a * a;          // a_full
                const size_t NL = (size_t)NCUR * LFULL;

                float s, c;
                sincosf(alpha[jg], &s, &c);
                const size_t o = (size_t)n * LFULL + jg;
                out[o]          = a * (c - 1.f);         // xp
                out[NL + o]     = bsq * s;               // yp
                out[2 * NL + o] = -a * s;                // xp'
                out[3 * NL + o] = fmaf(bsq, c, dbv * s); // yp'

                if (jg < BHALF - 1) {                    // mirror l = 4096 - jg
                    const int l = 2 * (BHALF - 1) - jg;
                    float s2, c2;
                    sincosf(alpha[l], &s2, &c2);
                    const size_t o2 = (size_t)n * LFULL + l;
                    out[o2]          = a * (c2 - 1.f);
                    out[NL + o2]     = bsq * s2;
                    out[2 * NL + o2] = -a * s2;
                    out[3 * NL + o2] = fmaf(bsq, c2, -dbv * s2);  // db mirrored with -
                }
            }
        }
    }
}

extern "C" void kernel_launch(void* const* d_in, const int* in_sizes, int n_in,
                              void* d_out, int out_size) {
    (void)in_sizes; (void)n_in; (void)out_size;
    const float* alpha  = (const float*)d_in[0];
    const float* w0     = (const float*)d_in[1];
    const float* w1     = (const float*)d_in[2];
    const float* w2     = (const float*)d_in[3];
    const float* w3     = (const float*)d_in[4];
    const float* b0     = (const float*)d_in[5];
    const float* b1     = (const float*)d_in[6];
    const float* b2     = (const float*)d_in[7];
    const float* b3     = (const float*)d_in[8];
    const float* sqrt_a = (const float*)d_in[9];
    float* out = (float*)d_out;

    cudaFuncSetAttribute(sofa_kernel, cudaFuncAttributeMaxDynamicSharedMemorySize,
                         (int)SMEM_BYTES);

    dim3 grid(NTILES, NCUR);   // (17, 128)
    sofa_kernel<<<grid, NTHREADS, SMEM_BYTES>>>(alpha, w0, w1, w2, w3,
                                                b0, b1, b2, b3, sqrt_a, out);
}